// round 6
// baseline (speedup 1.0000x reference)
#include <cuda_runtime.h>
#include <stdint.h>

#define B_ 32
#define C_ 3
#define H_ 512
#define W_ 512
#define G_ 8
#define BINS_ 256
#define CLIPV_ 32
#define NPLANES_ (B_*C_)          // 96
#define NTILES_ (NPLANES_*G_*G_)  // 6144
#define PLANE_PX_ (H_*W_)         // 262144
#define PAD_ 9                    // interp tile lag (covers all LUT deps)

__device__ unsigned char g_img[NPLANES_ * PLANE_PX_];   // 25 MB quantized image
__device__ unsigned char g_lut[NTILES_ * BINS_];        // 1.5 MB LUTs
__device__ int           g_flag[NTILES_];               // per-tile LUT-ready flags

__global__ void init_flags_kernel() {
    g_flag[blockIdx.x * 256 + threadIdx.x] = 0;
}

// ---------------------------------------------------------------------------
// Fused kernel. Block b:
//   Phase A (b < NTILES): quantize + histogram tile b, clip/redistribute/scan,
//     write LUT + quantized image, fence, raise flag[b].
//   Phase B (b >= PAD): tile t = b - PAD. Spin on the <=9 neighbor flags
//     (all set by blocks <= b -> deadlock-free under in-order dispatch),
//     build packed qlut in smem, dp2a bilinear interp, streaming store.
// ---------------------------------------------------------------------------
__global__ __launch_bounds__(256) void fused_kernel(const float* __restrict__ x,
                                                    float* __restrict__ out) {
    const int b = blockIdx.x;
    const int t = threadIdx.x;
    const int lane = t & 31;
    const int warp = t >> 5;

    __shared__ int      hist[2 * BINS_];
    __shared__ int      wsum[8];
    __shared__ uint32_t qlut[4 * BINS_];

    // ===================== Phase A: histogram + LUT for tile b ==============
    if (b < NTILES_) {
        const int plane = b >> 6;
        const int gy    = (b >> 3) & 7;
        const int gx    = b & 7;

        hist[t] = 0;
        hist[t + 256] = 0;
        __syncthreads();

        int* myhist = hist + ((warp & 4) << 6);   // warps 0-3 / 4-7 split

        const float*   p = x     + (size_t)plane * PLANE_PX_;
        unsigned char* q = g_img + (size_t)plane * PLANE_PX_;

        #pragma unroll
        for (int i = 0; i < 4; i++) {
            int p4 = i * 256 + t;
            int r  = p4 >> 4;
            int c  = (p4 & 15) << 2;
            size_t off = (size_t)(gy * 64 + r) * W_ + gx * 64 + c;
            float4 v = __ldcs(reinterpret_cast<const float4*>(p + off));
            int i0 = __float2int_rn(fminf(fmaxf(v.x, 0.0f), 1.0f) * 255.0f);
            int i1 = __float2int_rn(fminf(fmaxf(v.y, 0.0f), 1.0f) * 255.0f);
            int i2 = __float2int_rn(fminf(fmaxf(v.z, 0.0f), 1.0f) * 255.0f);
            int i3 = __float2int_rn(fminf(fmaxf(v.w, 0.0f), 1.0f) * 255.0f);
            uchar4 pk = make_uchar4((unsigned char)i0, (unsigned char)i1,
                                    (unsigned char)i2, (unsigned char)i3);
            *reinterpret_cast<uchar4*>(q + off) = pk;
            atomicAdd(&myhist[i0], 1);
            atomicAdd(&myhist[i1], 1);
            atomicAdd(&myhist[i2], 1);
            atomicAdd(&myhist[i3], 1);
        }
        __syncthreads();

        int h = hist[t] + hist[t + 256];
        int clipped = min(h, CLIPV_);
        int ex = h - clipped;
        #pragma unroll
        for (int o = 16; o > 0; o >>= 1) ex += __shfl_down_sync(0xffffffffu, ex, o);
        if (lane == 0) wsum[warp] = ex;
        __syncthreads();
        if (t == 0) {
            int s = 0;
            #pragma unroll
            for (int i = 0; i < 8; i++) s += wsum[i];
            wsum[0] = s;
        }
        __syncthreads();
        const int excess    = wsum[0];
        const int batch_add = excess >> 8;
        const int residual  = excess - (batch_add << 8);
        const int step      = max(BINS_ / max(residual, 1), 1);
        const int add       = ((t % step) == 0 && (t / step) < residual) ? 1 : 0;
        int hf = clipped + batch_add + add;

        int inc = hf;
        #pragma unroll
        for (int o = 1; o < 32; o <<= 1) {
            int n = __shfl_up_sync(0xffffffffu, inc, o);
            if (lane >= o) inc += n;
        }
        __syncthreads();
        if (lane == 31) wsum[warp] = inc;
        __syncthreads();
        if (t == 0) {
            int s = 0;
            #pragma unroll
            for (int i = 0; i < 8; i++) { int tmp = wsum[i]; wsum[i] = s; s += tmp; }
        }
        __syncthreads();
        float cdf = (float)(inc + wsum[warp]);

        float lut = rintf(cdf * (255.0f / 4096.0f));
        g_lut[(size_t)b * BINS_ + t] = (unsigned char)lut;

        // Publish: img + lut visible before flag.
        __threadfence();
        __syncthreads();
        if (t == 0) atomicExch(&g_flag[b], 1);
    }

    // ===================== Phase B: interp tile b - PAD ====================
    if (b >= PAD_) {
        const int tile  = b - PAD_;
        const int plane = tile >> 6;
        const int gy    = (tile >> 3) & 7;
        const int gx    = tile & 7;

        // Wait for the (up to) 9 neighbor LUTs (all from blocks <= b).
        if (t < 9) {
            int rr = min(max(gy + (t / 3) - 1, 0), G_ - 1);
            int cc = min(max(gx + (t % 3) - 1, 0), G_ - 1);
            int dep = (plane << 6) + rr * G_ + cc;
            volatile int* vf = g_flag;
            while (vf[dep] == 0) { __nanosleep(32); }
            __threadfence();   // acquire
        }
        __syncthreads();

        const unsigned char* lutp = g_lut + (size_t)plane * (G_ * G_ * BINS_);

        const int r_top[2] = { max(gy - 1, 0), gy };
        const int r_bot[2] = { gy, min(gy + 1, G_ - 1) };
        const int c_lft[2] = { max(gx - 1, 0), gx };
        const int c_rgt[2] = { gx, min(gx + 1, G_ - 1) };

        #pragma unroll
        for (int qd = 0; qd < 4; qd++) {
            const int* rr = (qd & 2) ? r_bot : r_top;
            const int* cc = (qd & 1) ? c_rgt : c_lft;
            uint32_t b0 = lutp[(rr[0] * G_ + cc[0]) * BINS_ + t];
            uint32_t b1 = lutp[(rr[0] * G_ + cc[1]) * BINS_ + t];
            uint32_t b2 = lutp[(rr[1] * G_ + cc[0]) * BINS_ + t];
            uint32_t b3 = lutp[(rr[1] * G_ + cc[1]) * BINS_ + t];
            qlut[(qd << 8) + t] = b0 | (b1 << 8) | (b2 << 16) | (b3 << 24);
        }
        __syncthreads();

        const unsigned char* img = g_img + (size_t)plane * PLANE_PX_;
        float* op = out + (size_t)plane * PLANE_PX_;

        const int tr    = t >> 4;           // 0..15
        const int c4    = (t & 15) << 2;    // 0..60
        const int xhalf = (c4 >= 32) ? 1 : 0;

        uint32_t packedX[4];
        #pragma unroll
        for (int k = 0; k < 4; k++) {
            uint32_t WX = (uint32_t)((c4 + k + 32) & 63);
            packedX[k] = (64u - WX) | (WX << 16);
        }

        #pragma unroll
        for (int i = 0; i < 4; i++) {
            const int r = i * 16 + tr;
            const int y = gy * 64 + r;
            const uint32_t WY  = (uint32_t)((r + 32) & 63);
            const uint32_t wyb = WY;
            const uint32_t wyt = 64u - WY;
            const uint32_t* ql = &qlut[(((r >= 32) ? 2 : 0) + xhalf) << 8];

            const size_t off = (size_t)y * W_ + gx * 64 + c4;
            uchar4 pix = *reinterpret_cast<const uchar4*>(img + off);
            int vs[4] = { pix.x, pix.y, pix.z, pix.w };

            float res[4];
            #pragma unroll
            for (int k = 0; k < 4; k++) {
                uint32_t pk   = ql[vs[k]];
                uint32_t Wtop = wyt * packedX[k];
                uint32_t Wbot = wyb * packedX[k];
                uint32_t acc  = __dp2a_lo(Wtop, pk, 0u);
                acc           = __dp2a_hi(Wbot, pk, acc);
                float rr = (float)(int)acc;
                res[k] = rintf(rr * (1.0f / 4096.0f)) * (1.0f / 255.0f);
            }
            __stcs(reinterpret_cast<float4*>(op + off),
                   make_float4(res[0], res[1], res[2], res[3]));
        }
    }
}

extern "C" void kernel_launch(void* const* d_in, const int* in_sizes, int n_in,
                              void* d_out, int out_size) {
    const float* x = (const float*)d_in[0];
    float* out = (float*)d_out;

    init_flags_kernel<<<NTILES_ / 256, 256>>>();
    fused_kernel<<<NTILES_ + PAD_, 256>>>(x, out);
}

// round 7
// speedup vs baseline: 1.2507x; 1.2507x over previous
#include <cuda_runtime.h>
#include <stdint.h>

#define B_ 32
#define C_ 3
#define H_ 512
#define W_ 512
#define G_ 8
#define BINS_ 256
#define CLIPV_ 32
#define NPLANES_ (B_*C_)          // 96
#define NTILES_ (NPLANES_*G_*G_)  // 6144
#define PLANE_PX_ (H_*W_)         // 262144

#define MAGIC_ 12582912.0f        // 1.5 * 2^23: FADD rounds to integer, half-even

__device__ unsigned char g_img[NPLANES_ * PLANE_PX_];   // 25 MB quantized image
__device__ unsigned char g_lut[NTILES_ * BINS_];        // 1.5 MB LUTs

// ---------------------------------------------------------------------------
// Kernel 1: per-tile histogram -> clip -> redistribute -> cdf -> LUT
// Magic-add quantization (no F2I). Dual sub-histograms.
// ---------------------------------------------------------------------------
__global__ __launch_bounds__(256) void hist_lut_kernel(const float* __restrict__ x) {
    const int tile  = blockIdx.x;
    const int plane = tile >> 6;
    const int gy    = (tile >> 3) & 7;
    const int gx    = tile & 7;

    __shared__ int hist[2 * BINS_];
    __shared__ int wsum[8];

    const int t    = threadIdx.x;
    const int lane = t & 31;
    const int warp = t >> 5;
    hist[t] = 0;
    hist[t + 256] = 0;
    __syncthreads();

    int* myhist = hist + ((warp & 4) << 6);

    const float*   p = x     + (size_t)plane * PLANE_PX_;
    unsigned char* q = g_img + (size_t)plane * PLANE_PX_;

    #pragma unroll
    for (int i = 0; i < 4; i++) {
        int p4 = i * 256 + t;
        int r  = p4 >> 4;
        int c  = (p4 & 15) << 2;
        size_t off = (size_t)(gy * 64 + r) * W_ + gx * 64 + c;
        float4 v = __ldcs(reinterpret_cast<const float4*>(p + off));
        // clamp, *255 (FMUL rounds like the reference), magic-add to round
        uint32_t q0 = __float_as_uint(fminf(fmaxf(v.x, 0.0f), 1.0f) * 255.0f + MAGIC_);
        uint32_t q1 = __float_as_uint(fminf(fmaxf(v.y, 0.0f), 1.0f) * 255.0f + MAGIC_);
        uint32_t q2 = __float_as_uint(fminf(fmaxf(v.z, 0.0f), 1.0f) * 255.0f + MAGIC_);
        uint32_t q3 = __float_as_uint(fminf(fmaxf(v.w, 0.0f), 1.0f) * 255.0f + MAGIC_);
        int i0 = q0 & 0xFF;
        int i1 = q1 & 0xFF;
        int i2 = q2 & 0xFF;
        int i3 = q3 & 0xFF;
        // pack the 4 low bytes -> one u32 store
        uint32_t lo = __byte_perm(q0, q1, 0x0040);   // q0.b0 | q1.b0<<8
        uint32_t hi = __byte_perm(q2, q3, 0x0040);   // q2.b0 | q3.b0<<8
        uint32_t pk = __byte_perm(lo, hi, 0x5410);
        *reinterpret_cast<uint32_t*>(q + off) = pk;
        atomicAdd(&myhist[i0], 1);
        atomicAdd(&myhist[i1], 1);
        atomicAdd(&myhist[i2], 1);
        atomicAdd(&myhist[i3], 1);
    }
    __syncthreads();

    int h = hist[t] + hist[t + 256];
    int clipped = min(h, CLIPV_);
    int ex = h - clipped;
    #pragma unroll
    for (int o = 16; o > 0; o >>= 1) ex += __shfl_down_sync(0xffffffffu, ex, o);
    if (lane == 0) wsum[warp] = ex;
    __syncthreads();
    if (t == 0) {
        int s = 0;
        #pragma unroll
        for (int i = 0; i < 8; i++) s += wsum[i];
        wsum[0] = s;
    }
    __syncthreads();
    const int excess    = wsum[0];
    const int batch_add = excess >> 8;
    const int residual  = excess - (batch_add << 8);
    const int step      = max(BINS_ / max(residual, 1), 1);
    const int add       = ((t % step) == 0 && (t / step) < residual) ? 1 : 0;
    int hf = clipped + batch_add + add;

    int inc = hf;
    #pragma unroll
    for (int o = 1; o < 32; o <<= 1) {
        int n = __shfl_up_sync(0xffffffffu, inc, o);
        if (lane >= o) inc += n;
    }
    __syncthreads();
    if (lane == 31) wsum[warp] = inc;
    __syncthreads();
    if (t == 0) {
        int s = 0;
        #pragma unroll
        for (int i = 0; i < 8; i++) { int tmp = wsum[i]; wsum[i] = s; s += tmp; }
    }
    __syncthreads();
    float cdf = (float)(inc + wsum[warp]);

    float lut = rintf(cdf * (255.0f / 4096.0f));
    g_lut[(size_t)tile * BINS_ + t] = (unsigned char)lut;
}

// ---------------------------------------------------------------------------
// Kernel 2: bilinear LUT interpolation, packed-u32 quadrant LUTs + dp2a.
// Conversion-free tail: bit-OR float construction + magic-FMA rounding.
// ---------------------------------------------------------------------------
__global__ __launch_bounds__(256) void interp_kernel(float* __restrict__ out) {
    const int tile  = blockIdx.x;
    const int plane = tile >> 6;
    const int gy    = (tile >> 3) & 7;
    const int gx    = tile & 7;

    __shared__ uint32_t qlut[4 * BINS_];

    const int t = threadIdx.x;
    const unsigned char* lutp = g_lut + (size_t)plane * (G_ * G_ * BINS_);

    const int r_top[2] = { max(gy - 1, 0), gy };
    const int r_bot[2] = { gy, min(gy + 1, G_ - 1) };
    const int c_lft[2] = { max(gx - 1, 0), gx };
    const int c_rgt[2] = { gx, min(gx + 1, G_ - 1) };

    #pragma unroll
    for (int qd = 0; qd < 4; qd++) {
        const int* rr = (qd & 2) ? r_bot : r_top;
        const int* cc = (qd & 1) ? c_rgt : c_lft;
        uint32_t b0 = lutp[(rr[0] * G_ + cc[0]) * BINS_ + t];
        uint32_t b1 = lutp[(rr[0] * G_ + cc[1]) * BINS_ + t];
        uint32_t b2 = lutp[(rr[1] * G_ + cc[0]) * BINS_ + t];
        uint32_t b3 = lutp[(rr[1] * G_ + cc[1]) * BINS_ + t];
        qlut[(qd << 8) + t] = b0 | (b1 << 8) | (b2 << 16) | (b3 << 24);
    }
    __syncthreads();

    const unsigned char* img = g_img + (size_t)plane * PLANE_PX_;
    float* op = out + (size_t)plane * PLANE_PX_;

    const int tr    = t >> 4;           // 0..15
    const int c4    = (t & 15) << 2;    // 0..60
    const int xhalf = (c4 >= 32) ? 1 : 0;

    uint32_t packedX[4];
    #pragma unroll
    for (int k = 0; k < 4; k++) {
        uint32_t WX = (uint32_t)((c4 + k + 32) & 63);
        packedX[k] = (64u - WX) | (WX << 16);
    }

    #pragma unroll
    for (int i = 0; i < 4; i++) {
        const int r = i * 16 + tr;
        const int y = gy * 64 + r;
        const uint32_t WY  = (uint32_t)((r + 32) & 63);
        const uint32_t wyb = WY;
        const uint32_t wyt = 64u - WY;
        const uint32_t* ql = &qlut[(((r >= 32) ? 2 : 0) + xhalf) << 8];

        const size_t off = (size_t)y * W_ + gx * 64 + c4;
        uchar4 pix = *reinterpret_cast<const uchar4*>(img + off);
        int vs[4] = { pix.x, pix.y, pix.z, pix.w };

        float res[4];
        #pragma unroll
        for (int k = 0; k < 4; k++) {
            uint32_t pk   = ql[vs[k]];
            uint32_t Wtop = wyt * packedX[k];
            uint32_t Wbot = wyb * packedX[k];
            uint32_t acc  = __dp2a_lo(Wtop, pk, 0u);
            acc           = __dp2a_hi(Wbot, pk, acc);
            // acc < 2^22 -> g = 2^23 + acc exactly (no I2F)
            float g = __uint_as_float(0x4B000000u | acc);
            // h = 12582912 + rint_even(acc/4096): single FMA rounding at ulp=1
            float h = fmaf(g, (1.0f / 4096.0f), MAGIC_ - 2048.0f);
            res[k]  = (h - MAGIC_) * (1.0f / 255.0f);
        }
        __stcs(reinterpret_cast<float4*>(op + off),
               make_float4(res[0], res[1], res[2], res[3]));
    }
}

extern "C" void kernel_launch(void* const* d_in, const int* in_sizes, int n_in,
                              void* d_out, int out_size) {
    const float* x = (const float*)d_in[0];
    float* out = (float*)d_out;

    hist_lut_kernel<<<NTILES_, 256>>>(x);
    interp_kernel<<<NTILES_, 256>>>(out);
}